// round 1
// baseline (speedup 1.0000x reference)
#include <cuda_runtime.h>

#define DD 128
#define MAXN 50000
#define GG 64

// ---------------- device scratch (no allocations allowed) ----------------
__device__ float g_h[(size_t)MAXN * DD];     // h = lin1(node_h); later reused for out2
__device__ float g_agg[(size_t)MAXN * DD];   // scatter-add target
__device__ float g_t[(size_t)MAXN * DD];     // t = silu(conv) + node_h
__device__ float g_sums[GG * DD];
__device__ float g_sq[GG * DD];
__device__ int   g_cnt[GG];
__device__ int   g_is64;                     // index dtype flag (int64 vs int32)

__device__ __forceinline__ long long ld_idx(const void* p, long long i, int is64) {
    return is64 ? ((const long long*)p)[i] : (long long)((const int*)p)[i];
}
__device__ __forceinline__ float silu_f(float x) { return x / (1.0f + __expf(-x)); }

// ---------------- dtype detection ----------------
// If indices are int64 (little-endian, values < 2^31), every odd 32-bit word is 0.
// For int32 data those words are random indices in [0, 50000): P(all 64 zero) ~ 0.
__global__ void k_detect(const unsigned* __restrict__ ei) {
    int all0 = 1;
    for (int i = 0; i < 64; i++) all0 &= (ei[2 * i + 1] == 0u);
    g_is64 = all0;
}

__global__ void k_zero(int Nn) {
    long long i = (long long)blockIdx.x * blockDim.x + threadIdx.x;
    long long step = (long long)gridDim.x * blockDim.x;
    long long tot = (long long)Nn * DD;
    for (long long k = i; k < tot; k += step) g_agg[k] = 0.f;
    for (long long k = i; k < GG * DD; k += step) { g_sums[k] = 0.f; g_sq[k] = 0.f; }
    if (i < GG) g_cnt[(int)i] = 0;
}

// ---------------- GEMM building blocks ----------------
// 128x128 tile, 256 threads, 8x8 microtile per thread, K chunked by 16,
// full 128x128 weight (transposed: Ws[k*128+c] = W[c*128+k]) resident in smem.
struct Frag { float4 v[2]; };

__device__ __forceinline__ void ldg_chunk(Frag& f, const float* __restrict__ src,
                                          long long r0, int kk, long long rows, int tid) {
#pragma unroll
    for (int l = 0; l < 2; l++) {
        int idx = tid * 2 + l;     // 0..511
        int e = idx >> 2;          // 0..127 (row within tile)
        int kq = idx & 3;          // 0..3  (float4 within 16-wide k chunk)
        long long r = r0 + e;
        float4 x = make_float4(0.f, 0.f, 0.f, 0.f);
        if (r < rows) x = *(const float4*)(src + r * DD + kk + kq * 4);
        f.v[l] = x;
    }
}
__device__ __forceinline__ void sts_chunk(const Frag& f, float* dst, int tid) {
#pragma unroll
    for (int l = 0; l < 2; l++) {
        int idx = tid * 2 + l;
        int e = idx >> 2, kq = idx & 3;
        dst[(kq * 4 + 0) * 128 + e] = f.v[l].x;
        dst[(kq * 4 + 1) * 128 + e] = f.v[l].y;
        dst[(kq * 4 + 2) * 128 + e] = f.v[l].z;
        dst[(kq * 4 + 3) * 128 + e] = f.v[l].w;
    }
}
__device__ __forceinline__ void mma_chunk(float acc[8][8], const float* As,
                                          const float* Ws, int kk, int tx, int ty) {
#pragma unroll
    for (int k = 0; k < 16; k++) {
        float4 a0 = *(const float4*)(As + k * 128 + ty * 8);
        float4 a1 = *(const float4*)(As + k * 128 + ty * 8 + 4);
        float4 b0 = *(const float4*)(Ws + (kk + k) * 128 + tx * 8);
        float4 b1 = *(const float4*)(Ws + (kk + k) * 128 + tx * 8 + 4);
        float a[8] = {a0.x, a0.y, a0.z, a0.w, a1.x, a1.y, a1.z, a1.w};
        float b[8] = {b0.x, b0.y, b0.z, b0.w, b1.x, b1.y, b1.z, b1.w};
#pragma unroll
        for (int i = 0; i < 8; i++)
#pragma unroll
            for (int j = 0; j < 8; j++)
                acc[i][j] = fmaf(a[i], b[j], acc[i][j]);
    }
}

// ---------------- kernel 1: h = node_h @ w1^T + b1 ----------------
__global__ __launch_bounds__(256, 2) void k_node(const float* __restrict__ X,
                                                 const float* __restrict__ W,
                                                 const float* __restrict__ bias, int Nn) {
    extern __shared__ float sm[];
    float* Ws = sm;            // 16384 floats
    float* As = sm + 16384;    // 2 * 2048 floats
    int tid = threadIdx.x, tx = tid & 15, ty = tid >> 4;
    for (int i = tid; i < 16384; i += 256) {
        int c = i >> 7, k = i & 127;
        Ws[k * 128 + c] = W[i];
    }
    long long r0 = (long long)blockIdx.x * 128;
    float acc[8][8];
#pragma unroll
    for (int i = 0; i < 8; i++)
#pragma unroll
        for (int j = 0; j < 8; j++) acc[i][j] = 0.f;

    Frag f;
    ldg_chunk(f, X, r0, 0, Nn, tid);
    sts_chunk(f, As, tid);
    __syncthreads();
#pragma unroll 1
    for (int c = 0; c < 8; c++) {
        int kk = c * 16, cur = c & 1;
        if (c < 7) ldg_chunk(f, X, r0, kk + 16, Nn, tid);
        mma_chunk(acc, As + cur * 2048, Ws, kk, tx, ty);
        if (c < 7) sts_chunk(f, As + (cur ^ 1) * 2048, tid);
        __syncthreads();
    }
    float4 bb0 = *(const float4*)(bias + tx * 8);
    float4 bb1 = *(const float4*)(bias + tx * 8 + 4);
    float bl[8] = {bb0.x, bb0.y, bb0.z, bb0.w, bb1.x, bb1.y, bb1.z, bb1.w};
#pragma unroll
    for (int i = 0; i < 8; i++) {
        long long r = r0 + ty * 8 + i;
        if (r < Nn) {
            float4 o0 = make_float4(acc[i][0] + bl[0], acc[i][1] + bl[1],
                                    acc[i][2] + bl[2], acc[i][3] + bl[3]);
            float4 o1 = make_float4(acc[i][4] + bl[4], acc[i][5] + bl[5],
                                    acc[i][6] + bl[6], acc[i][7] + bl[7]);
            *(float4*)(g_h + r * DD + tx * 8) = o0;
            *(float4*)(g_h + r * DD + tx * 8 + 4) = o1;
        }
    }
}

// ---- kernel 2: fused edge GEMM + gather h[src] + SiLU + scatter-add to agg[dst] ----
__global__ __launch_bounds__(256, 2) void k_edge(const float* __restrict__ EA,
                                                 const float* __restrict__ W,
                                                 const float* __restrict__ bias,
                                                 const void* __restrict__ ei,
                                                 int Ee, int Nn) {
    extern __shared__ float sm[];
    float* Ws = sm;
    float* As = sm + 16384;
    int tid = threadIdx.x, tx = tid & 15, ty = tid >> 4;
    for (int i = tid; i < 16384; i += 256) {
        int c = i >> 7, k = i & 127;
        Ws[k * 128 + c] = W[i];
    }
    long long r0 = (long long)blockIdx.x * 128;
    float acc[8][8];
#pragma unroll
    for (int i = 0; i < 8; i++)
#pragma unroll
        for (int j = 0; j < 8; j++) acc[i][j] = 0.f;

    Frag f;
    ldg_chunk(f, EA, r0, 0, Ee, tid);
    sts_chunk(f, As, tid);
    __syncthreads();
#pragma unroll 1
    for (int c = 0; c < 8; c++) {
        int kk = c * 16, cur = c & 1;
        if (c < 7) ldg_chunk(f, EA, r0, kk + 16, Ee, tid);
        mma_chunk(acc, As + cur * 2048, Ws, kk, tx, ty);
        if (c < 7) sts_chunk(f, As + (cur ^ 1) * 2048, tid);
        __syncthreads();
    }
    float4 bb0 = *(const float4*)(bias + tx * 8);
    float4 bb1 = *(const float4*)(bias + tx * 8 + 4);
    float bl[8] = {bb0.x, bb0.y, bb0.z, bb0.w, bb1.x, bb1.y, bb1.z, bb1.w};
    int is64 = g_is64;
#pragma unroll
    for (int i = 0; i < 8; i++) {
        long long e = r0 + ty * 8 + i;
        if (e < Ee) {
            long long s = ld_idx(ei, e, is64);
            long long d = ld_idx(ei, (long long)Ee + e, is64);
            const float* hp = g_h + s * DD + tx * 8;
            float4 h0 = *(const float4*)hp;
            float4 h1 = *(const float4*)(hp + 4);
            float hv[8] = {h0.x, h0.y, h0.z, h0.w, h1.x, h1.y, h1.z, h1.w};
            float* ap = g_agg + d * DD + tx * 8;
#pragma unroll
            for (int j = 0; j < 8; j++) {
                float m = silu_f(acc[i][j] + bl[j] + hv[j]);
                atomicAdd(ap + j, m);
            }
        }
    }
}

// ---- kernel 3: t = silu((1+eps)h + agg) + node_h; per-graph sums (run-length) ----
__global__ void k_post1(const float* __restrict__ X, const void* __restrict__ batch,
                        const float* __restrict__ epsp, int Nn) {
    int c = threadIdx.x & 127;
    int half = threadIdx.x >> 7;
    long long n0 = (long long)blockIdx.x * 64 + half * 32;
    float ep = 1.0f + epsp[0];
    int is64 = g_is64;
    int curg = -1; float accv = 0.f; int cr = 0;
    for (int q = 0; q < 32; q++) {
        long long n = n0 + q;
        if (n >= Nn) break;
        long long off = n * DD + c;
        float conv = ep * g_h[off] + g_agg[off];
        float t = silu_f(conv) + X[off];
        g_t[off] = t;
        int g = (int)ld_idx(batch, n, is64);
        if (g != curg) {
            if (curg >= 0) {
                atomicAdd(&g_sums[curg * DD + c], accv);
                if (c == 0) atomicAdd(&g_cnt[curg], cr);
            }
            curg = g; accv = t; cr = 1;
        } else { accv += t; cr++; }
    }
    if (curg >= 0) {
        atomicAdd(&g_sums[curg * DD + c], accv);
        if (c == 0) atomicAdd(&g_cnt[curg], cr);
    }
}

// ---- kernel 4: out2 = t - mean[batch]*mean_scale; per-graph sq sums ----
__global__ void k_post2(const void* __restrict__ batch, const float* __restrict__ gms,
                        int Nn) {
    int c = threadIdx.x & 127;
    int half = threadIdx.x >> 7;
    long long n0 = (long long)blockIdx.x * 64 + half * 32;
    int is64 = g_is64;
    float msc = gms[c];
    int curg = -1; float mean = 0.f, ssq = 0.f;
    for (int q = 0; q < 32; q++) {
        long long n = n0 + q;
        if (n >= Nn) break;
        int g = (int)ld_idx(batch, n, is64);
        if (g != curg) {
            if (curg >= 0) atomicAdd(&g_sq[curg * DD + c], ssq);
            curg = g; ssq = 0.f;
            float cf = fmaxf((float)g_cnt[g], 1.f);
            mean = g_sums[g * DD + c] / cf;
        }
        long long off = n * DD + c;
        float o = g_t[off] - mean * msc;
        g_h[off] = o;   // reuse g_h as out2 buffer
        ssq += o * o;
    }
    if (curg >= 0) atomicAdd(&g_sq[curg * DD + c], ssq);
}

// ---- kernel 5: out = weight * out2 / std + bias ----
__global__ void k_post3(const void* __restrict__ batch, const float* __restrict__ gw,
                        const float* __restrict__ gb, float* __restrict__ out, int Nn) {
    long long i = (long long)blockIdx.x * blockDim.x + threadIdx.x;
    long long step = (long long)gridDim.x * blockDim.x;
    long long tot = (long long)Nn * DD;
    int is64 = g_is64;
    for (long long k = i; k < tot; k += step) {
        long long n = k >> 7;
        int c = (int)(k & 127);
        int g = (int)ld_idx(batch, n, is64);
        float cf = fmaxf((float)g_cnt[g], 1.f);
        float stdv = sqrtf(g_sq[g * DD + c] / cf + 1e-5f);
        out[k] = gw[c] * g_h[k] / stdv + gb[c];
    }
}

// ---------------- launcher ----------------
extern "C" void kernel_launch(void* const* d_in, const int* in_sizes, int n_in,
                              void* d_out, int out_size) {
    const float* node_h    = (const float*)d_in[0];
    const float* edge_attr = (const float*)d_in[1];
    const void*  batch     = d_in[2];
    const void*  ei        = d_in[3];
    const float* w1  = (const float*)d_in[4];
    const float* b1  = (const float*)d_in[5];
    const float* we  = (const float*)d_in[6];
    const float* be  = (const float*)d_in[7];
    const float* eps = (const float*)d_in[8];
    const float* gnw = (const float*)d_in[9];
    const float* gnb = (const float*)d_in[10];
    const float* gms = (const float*)d_in[11];

    int Nn = in_sizes[0] / DD;
    int Ee = in_sizes[1] / DD;

    size_t smem = (size_t)(16384 + 2 * 2048) * sizeof(float);   // 81920 B
    cudaFuncSetAttribute(k_node, cudaFuncAttributeMaxDynamicSharedMemorySize, (int)smem);
    cudaFuncSetAttribute(k_edge, cudaFuncAttributeMaxDynamicSharedMemorySize, (int)smem);

    k_detect<<<1, 1>>>((const unsigned*)ei);
    k_zero<<<1024, 256>>>(Nn);
    k_node<<<(Nn + 127) / 128, 256, smem>>>(node_h, w1, b1, Nn);
    k_edge<<<(Ee + 127) / 128, 256, smem>>>(edge_attr, we, be, ei, Ee, Nn);
    k_post1<<<(Nn + 63) / 64, 256>>>(node_h, batch, eps, Nn);
    k_post2<<<(Nn + 63) / 64, 256>>>(batch, gms, Nn);
    k_post3<<<2048, 256>>>(batch, gnw, gnb, (float*)d_out, Nn);
}

// round 7
// speedup vs baseline: 1.0619x; 1.0619x over previous
#include <cuda_runtime.h>
#include <cuda_bf16.h>
#include <cstdint>

#define DD 128
#define MAXN 50000
#define GG 64

// ---------------- device scratch ----------------
__device__ float g_h[(size_t)MAXN * DD];
__device__ float g_agg[(size_t)MAXN * DD];
__device__ float g_t[(size_t)MAXN * DD];
__device__ float g_sums[GG * DD];
__device__ float g_sq[GG * DD];
__device__ int   g_cnt[GG];
__device__ int   g_is64;
// bf16-split edge weight, row-major [n][k], 16B-aligned for uint4 copies
__device__ __align__(16) __nv_bfloat16 g_whi[16384];
__device__ __align__(16) __nv_bfloat16 g_wlo[16384];

__device__ __forceinline__ long long ld_idx(const void* p, long long i, int is64) {
    return is64 ? ((const long long*)p)[i] : (long long)((const int*)p)[i];
}
__device__ __forceinline__ float silu_f(float x) { return x / (1.0f + __expf(-x)); }

__device__ __forceinline__ uint32_t smem_u32(const void* p) {
    uint32_t a;
    asm("{ .reg .u64 t; cvta.to.shared.u64 t, %1; cvt.u32.u64 %0, t; }" : "=r"(a) : "l"(p));
    return a;
}
__device__ __forceinline__ void ldsm_x4(uint32_t* r, uint32_t addr) {
    asm volatile("ldmatrix.sync.aligned.m8n8.x4.shared.b16 {%0,%1,%2,%3}, [%4];"
                 : "=r"(r[0]), "=r"(r[1]), "=r"(r[2]), "=r"(r[3]) : "r"(addr));
}
__device__ __forceinline__ void mma_bf16(float* d, const uint32_t* a,
                                         uint32_t b0, uint32_t b1) {
    asm volatile("mma.sync.aligned.m16n8k16.row.col.f32.bf16.bf16.f32 "
                 "{%0,%1,%2,%3}, {%4,%5,%6,%7}, {%8,%9}, {%0,%1,%2,%3};"
                 : "+f"(d[0]), "+f"(d[1]), "+f"(d[2]), "+f"(d[3])
                 : "r"(a[0]), "r"(a[1]), "r"(a[2]), "r"(a[3]), "r"(b0), "r"(b1));
}
__device__ __forceinline__ uint32_t pack_bf16x2(float x, float y) {
    __nv_bfloat16 bx = __float2bfloat16(x), by = __float2bfloat16(y);
    return (uint32_t)__bfloat16_as_ushort(bx) | ((uint32_t)__bfloat16_as_ushort(by) << 16);
}

// ---------------- misc kernels ----------------
__global__ void k_detect(const unsigned* __restrict__ ei) {
    int all0 = 1;
    for (int i = 0; i < 64; i++) all0 &= (ei[2 * i + 1] == 0u);
    g_is64 = all0;
}

__global__ void k_zero(int Nn) {
    long long i = (long long)blockIdx.x * blockDim.x + threadIdx.x;
    long long step = (long long)gridDim.x * blockDim.x;
    long long tot = (long long)Nn * DD;
    for (long long k = i; k < tot; k += step) g_agg[k] = 0.f;
    for (long long k = i; k < GG * DD; k += step) { g_sums[k] = 0.f; g_sq[k] = 0.f; }
    if (i < GG) g_cnt[(int)i] = 0;
}

// split We into bf16 hi/lo, row-major [n][k]
__global__ void k_prep_w(const float* __restrict__ W) {
    int tid = threadIdx.x;
    for (int i = tid; i < 8192; i += 256) {
        int n = i >> 6, k2 = (i & 63) * 2;
        float2 w = *(const float2*)(W + n * DD + k2);
        __nv_bfloat16 h0 = __float2bfloat16(w.x), h1 = __float2bfloat16(w.y);
        float l0 = w.x - __bfloat162float(h0), l1 = w.y - __bfloat162float(h1);
        ((uint32_t*)g_whi)[i] = (uint32_t)__bfloat16_as_ushort(h0) |
                                ((uint32_t)__bfloat16_as_ushort(h1) << 16);
        ((uint32_t*)g_wlo)[i] = pack_bf16x2(l0, l1);
    }
}

// ---------------- SIMT GEMM for node lin1 ----------------
struct Frag { float4 v[2]; };
__device__ __forceinline__ void ldg_chunk(Frag& f, const float* __restrict__ src,
                                          long long r0, int kk, long long rows, int tid) {
#pragma unroll
    for (int l = 0; l < 2; l++) {
        int idx = tid * 2 + l;
        int e = idx >> 2, kq = idx & 3;
        long long r = r0 + e;
        float4 x = make_float4(0.f, 0.f, 0.f, 0.f);
        if (r < rows) x = *(const float4*)(src + r * DD + kk + kq * 4);
        f.v[l] = x;
    }
}
__device__ __forceinline__ void sts_chunk(const Frag& f, float* dst, int tid) {
#pragma unroll
    for (int l = 0; l < 2; l++) {
        int idx = tid * 2 + l;
        int e = idx >> 2, kq = idx & 3;
        dst[(kq * 4 + 0) * 128 + e] = f.v[l].x;
        dst[(kq * 4 + 1) * 128 + e] = f.v[l].y;
        dst[(kq * 4 + 2) * 128 + e] = f.v[l].z;
        dst[(kq * 4 + 3) * 128 + e] = f.v[l].w;
    }
}
__device__ __forceinline__ void mma_chunk(float acc[8][8], const float* As,
                                          const float* Ws, int kk, int tx, int ty) {
#pragma unroll
    for (int k = 0; k < 16; k++) {
        float4 a0 = *(const float4*)(As + k * 128 + ty * 8);
        float4 a1 = *(const float4*)(As + k * 128 + ty * 8 + 4);
        float4 b0 = *(const float4*)(Ws + (kk + k) * 128 + tx * 8);
        float4 b1 = *(const float4*)(Ws + (kk + k) * 128 + tx * 8 + 4);
        float a[8] = {a0.x, a0.y, a0.z, a0.w, a1.x, a1.y, a1.z, a1.w};
        float b[8] = {b0.x, b0.y, b0.z, b0.w, b1.x, b1.y, b1.z, b1.w};
#pragma unroll
        for (int i = 0; i < 8; i++)
#pragma unroll
            for (int j = 0; j < 8; j++)
                acc[i][j] = fmaf(a[i], b[j], acc[i][j]);
    }
}

__global__ __launch_bounds__(256, 2) void k_node(const float* __restrict__ X,
                                                 const float* __restrict__ W,
                                                 const float* __restrict__ bias, int Nn) {
    extern __shared__ float sm[];
    float* Ws = sm;
    float* As = sm + 16384;
    int tid = threadIdx.x, tx = tid & 15, ty = tid >> 4;
    for (int i = tid; i < 16384; i += 256) {
        int c = i >> 7, k = i & 127;
        Ws[k * 128 + c] = W[i];
    }
    long long r0 = (long long)blockIdx.x * 128;
    float acc[8][8];
#pragma unroll
    for (int i = 0; i < 8; i++)
#pragma unroll
        for (int j = 0; j < 8; j++) acc[i][j] = 0.f;
    Frag f;
    ldg_chunk(f, X, r0, 0, Nn, tid);
    sts_chunk(f, As, tid);
    __syncthreads();
#pragma unroll 1
    for (int c = 0; c < 8; c++) {
        int kk = c * 16, cur = c & 1;
        if (c < 7) ldg_chunk(f, X, r0, kk + 16, Nn, tid);
        mma_chunk(acc, As + cur * 2048, Ws, kk, tx, ty);
        if (c < 7) sts_chunk(f, As + (cur ^ 1) * 2048, tid);
        __syncthreads();
    }
    float4 bb0 = *(const float4*)(bias + tx * 8);
    float4 bb1 = *(const float4*)(bias + tx * 8 + 4);
    float bl[8] = {bb0.x, bb0.y, bb0.z, bb0.w, bb1.x, bb1.y, bb1.z, bb1.w};
#pragma unroll
    for (int i = 0; i < 8; i++) {
        long long r = r0 + ty * 8 + i;
        if (r < Nn) {
            float4 o0 = make_float4(acc[i][0] + bl[0], acc[i][1] + bl[1],
                                    acc[i][2] + bl[2], acc[i][3] + bl[3]);
            float4 o1 = make_float4(acc[i][4] + bl[4], acc[i][5] + bl[5],
                                    acc[i][6] + bl[6], acc[i][7] + bl[7]);
            *(float4*)(g_h + r * DD + tx * 8) = o0;
            *(float4*)(g_h + r * DD + tx * 8 + 4) = o1;
        }
    }
}

// ---------------- mma.sync edge kernel ----------------
// smem tiles: bf16 [128][128], row stride 272B (16B pad -> conflict-free ldmatrix)
#define TSTR 272
#define SM_AHI 0
#define SM_ALO 34816
#define SM_WHI 69632
#define SM_WLO 104448
#define SM_EDGE_TOTAL 139264
#define DSTR 132   // staged D row stride in floats

__global__ __launch_bounds__(256, 1) void k_edge_mma(const float* __restrict__ EA,
                                                     const float* __restrict__ bias,
                                                     const void* __restrict__ ei,
                                                     int Ee) {
    extern __shared__ char smem[];
    uint32_t sb = smem_u32(smem);
    int tid = threadIdx.x;
    int wid = tid >> 5, lane = tid & 31;
    long long r0 = (long long)blockIdx.x * 128;

    // copy pre-split W (row-major [n][k]) into padded smem tiles
    {
        const uint4* wh = (const uint4*)g_whi;
        const uint4* wl = (const uint4*)g_wlo;
        for (int i = tid; i < 2048; i += 256) {
            int row = i >> 4, q = i & 15;
            *(uint4*)(smem + SM_WHI + row * TSTR + q * 16) = wh[i];
            *(uint4*)(smem + SM_WLO + row * TSTR + q * 16) = wl[i];
        }
    }
    // fill A hi/lo tiles from edge_attr
    for (int i = tid; i < 4096; i += 256) {
        int row = i >> 5, q = i & 31;           // q: float4 within row
        float4 a = make_float4(0.f, 0.f, 0.f, 0.f);
        if (r0 + row < Ee) a = *(const float4*)(EA + (r0 + row) * DD + q * 4);
        __nv_bfloat16 h0 = __float2bfloat16(a.x), h1 = __float2bfloat16(a.y);
        __nv_bfloat16 h2 = __float2bfloat16(a.z), h3 = __float2bfloat16(a.w);
        uint2 hv, lv;
        hv.x = (uint32_t)__bfloat16_as_ushort(h0) | ((uint32_t)__bfloat16_as_ushort(h1) << 16);
        hv.y = (uint32_t)__bfloat16_as_ushort(h2) | ((uint32_t)__bfloat16_as_ushort(h3) << 16);
        lv.x = pack_bf16x2(a.x - __bfloat162float(h0), a.y - __bfloat162float(h1));
        lv.y = pack_bf16x2(a.z - __bfloat162float(h2), a.w - __bfloat162float(h3));
        *(uint2*)(smem + SM_AHI + row * TSTR + q * 8) = hv;
        *(uint2*)(smem + SM_ALO + row * TSTR + q * 8) = lv;
    }
    __syncthreads();

    // 3-pass split GEMM: Ahi*Whi + Ahi*Wlo + Alo*Whi
    float acc[16][4];
#pragma unroll
    for (int i = 0; i < 16; i++)
#pragma unroll
        for (int j = 0; j < 4; j++) acc[i][j] = 0.f;

    int l16 = lane & 15;
    int lhalf = (lane >> 4) * 16;       // 16B column offset within ldmatrix
    uint32_t arow = (uint32_t)(wid * 16 + l16) * TSTR + lhalf;

#pragma unroll 1
    for (int pass = 0; pass < 3; pass++) {
        uint32_t Ab = sb + (pass == 2 ? SM_ALO : SM_AHI);
        uint32_t Wb = sb + (pass == 1 ? SM_WLO : SM_WHI);
#pragma unroll 1
        for (int ks = 0; ks < 8; ks++) {
            uint32_t a[4];
            ldsm_x4(a, Ab + arow + ks * 32);
#pragma unroll
            for (int nbp = 0; nbp < 8; nbp++) {
                uint32_t b[4];
                ldsm_x4(b, Wb + (uint32_t)(nbp * 16 + l16) * TSTR + lhalf + ks * 32);
                // b0=[n0-7,k0-7] b1=[n8-15,k0-7] b2=[n0-7,k8-15] b3=[n8-15,k8-15]
                mma_bf16(acc[2 * nbp], a, b[0], b[2]);
                mma_bf16(acc[2 * nbp + 1], a, b[1], b[3]);
            }
        }
    }
    __syncthreads();

    // stage D into smem (reuse A region) for contiguous epilogue access
    float* Ds = (float*)smem;
    {
        int rb = wid * 16 + (lane >> 2);
        int cb = (lane & 3) * 2;
#pragma unroll
        for (int nb = 0; nb < 16; nb++) {
            *(float2*)&Ds[rb * DSTR + nb * 8 + cb] = make_float2(acc[nb][0], acc[nb][1]);
            *(float2*)&Ds[(rb + 8) * DSTR + nb * 8 + cb] = make_float2(acc[nb][2], acc[nb][3]);
        }
    }
    __syncthreads();

    // epilogue: gather h[src], +bias, SiLU, scatter-add to agg[dst]
    int row = tid >> 1, ch = (tid & 1) * 64;
    long long e = r0 + row;
    if (e < Ee) {
        int is64 = g_is64;
        long long s = ld_idx(ei, e, is64);
        long long d = ld_idx(ei, (long long)Ee + e, is64);
        const float* hp = g_h + s * DD + ch;
        const float* bp = bias + ch;
        float* ap = g_agg + d * DD + ch;
#pragma unroll
        for (int j = 0; j < 16; j++) {
            float4 dv = *(const float4*)&Ds[row * DSTR + ch + j * 4];
            float4 hv = *(const float4*)(hp + j * 4);
            float4 bb = *(const float4*)(bp + j * 4);
            atomicAdd(ap + j * 4 + 0, silu_f(dv.x + bb.x + hv.x));
            atomicAdd(ap + j * 4 + 1, silu_f(dv.y + bb.y + hv.y));
            atomicAdd(ap + j * 4 + 2, silu_f(dv.z + bb.z + hv.z));
            atomicAdd(ap + j * 4 + 3, silu_f(dv.w + bb.w + hv.w));
        }
    }
}

// ---------------- post kernels (GraphNorm) ----------------
__global__ void k_post1(const float* __restrict__ X, const void* __restrict__ batch,
                        const float* __restrict__ epsp, int Nn) {
    int c = threadIdx.x & 127;
    int half = threadIdx.x >> 7;
    long long n0 = (long long)blockIdx.x * 64 + half * 32;
    float ep = 1.0f + epsp[0];
    int is64 = g_is64;
    int curg = -1; float accv = 0.f; int cr = 0;
    for (int q = 0; q < 32; q++) {
        long long n = n0 + q;
        if (n >= Nn) break;
        long long off = n * DD + c;
        float conv = ep * g_h[off] + g_agg[off];
        float t = silu_f(conv) + X[off];
        g_t[off] = t;
        int g = (int)ld_idx(batch, n, is64);
        if (g != curg) {
            if (curg >= 0) {
                atomicAdd(&g_sums[curg * DD + c], accv);
                if (c == 0) atomicAdd(&g_cnt[curg], cr);
            }
            curg = g; accv = t; cr = 1;
        } else { accv += t; cr++; }
    }
    if (curg >= 0) {
        atomicAdd(&g_sums[curg * DD + c], accv);
        if (c == 0) atomicAdd(&g_cnt[curg], cr);
    }
}

__global__ void k_post2(const void* __restrict__ batch, const float* __restrict__ gms,
                        int Nn) {
    int c = threadIdx.x & 127;
    int half = threadIdx.x >> 7;
    long long n0 = (long long)blockIdx.x * 64 + half * 32;
    int is64 = g_is64;
    float msc = gms[c];
    int curg = -1; float mean = 0.f, ssq = 0.f;
    for (int q = 0; q < 32; q++) {
        long long n = n0 + q;
        if (n >= Nn) break;
        int g = (int)ld_idx(batch, n, is64);
        if (g != curg) {
            if (curg >= 0) atomicAdd(&g_sq[curg * DD + c], ssq);
            curg = g; ssq = 0.f;
            float cf = fmaxf((float)g_cnt[g], 1.f);
            mean = g_sums[g * DD + c] / cf;
        }
        long long off = n * DD + c;
        float o = g_t[off] - mean * msc;
        g_h[off] = o;
        ssq += o * o;
    }
    if (curg >= 0) atomicAdd(&g_sq[curg * DD + c], ssq);
}

__global__ void k_post3(const void* __restrict__ batch, const float* __restrict__ gw,
                        const float* __restrict__ gb, float* __restrict__ out, int Nn) {
    long long i = (long long)blockIdx.x * blockDim.x + threadIdx.x;
    long long step = (long long)gridDim.x * blockDim.x;
    long long tot = (long long)Nn * DD;
    int is64 = g_is64;
    for (long long k = i; k < tot; k += step) {
        long long n = k >> 7;
        int c = (int)(k & 127);
        int g = (int)ld_idx(batch, n, is64);
        float cf = fmaxf((float)g_cnt[g], 1.f);
        float stdv = sqrtf(g_sq[g * DD + c] / cf + 1e-5f);
        out[k] = gw[c] * g_h[k] / stdv + gb[c];
    }
}

// ---------------- launcher ----------------
extern "C" void kernel_launch(void* const* d_in, const int* in_sizes, int n_in,
                              void* d_out, int out_size) {
    const float* node_h    = (const float*)d_in[0];
    const float* edge_attr = (const float*)d_in[1];
    const void*  batch     = d_in[2];
    const void*  ei        = d_in[3];
    const float* w1  = (const float*)d_in[4];
    const float* b1  = (const float*)d_in[5];
    const float* we  = (const float*)d_in[6];
    const float* be  = (const float*)d_in[7];
    const float* eps = (const float*)d_in[8];
    const float* gnw = (const float*)d_in[9];
    const float* gnb = (const float*)d_in[10];
    const float* gms = (const float*)d_in[11];

    int Nn = in_sizes[0] / DD;
    int Ee = in_sizes[1] / DD;

    size_t smem_node = (size_t)(16384 + 2 * 2048) * sizeof(float);
    cudaFuncSetAttribute(k_node, cudaFuncAttributeMaxDynamicSharedMemorySize, (int)smem_node);
    cudaFuncSetAttribute(k_edge_mma, cudaFuncAttributeMaxDynamicSharedMemorySize,
                         SM_EDGE_TOTAL);

    k_detect<<<1, 1>>>((const unsigned*)ei);
    k_zero<<<1024, 256>>>(Nn);
    k_prep_w<<<1, 256>>>(we);
    k_node<<<(Nn + 127) / 128, 256, smem_node>>>(node_h, w1, b1, Nn);
    k_edge_mma<<<(Ee + 127) / 128, 256, SM_EDGE_TOTAL>>>(edge_attr, be, ei, Ee);
    k_post1<<<(Nn + 63) / 64, 256>>>(node_h, batch, eps, Nn);
    k_post2<<<(Nn + 63) / 64, 256>>>(batch, gms, Nn);
    k_post3<<<2048, 256>>>(batch, gnw, gnb, (float*)d_out, Nn);
}

// round 8
// speedup vs baseline: 1.2808x; 1.2062x over previous
#include <cuda_runtime.h>
#include <cuda_bf16.h>
#include <cstdint>

#define DD 128
#define MAXN 50000
#define GG 64

// ---------------- device scratch ----------------
__device__ float g_h[(size_t)MAXN * DD];
__device__ float g_agg[(size_t)MAXN * DD];
__device__ float g_t[(size_t)MAXN * DD];
__device__ float g_sums[GG * DD];
__device__ float g_sq[GG * DD];
__device__ int   g_cnt[GG];
__device__ int   g_is64;
// bf16-split weights, row-major [n][k], 16B-aligned
__device__ __align__(16) __nv_bfloat16 g_whi[16384];   // edge lin
__device__ __align__(16) __nv_bfloat16 g_wlo[16384];
__device__ __align__(16) __nv_bfloat16 g_w1hi[16384];  // node lin1
__device__ __align__(16) __nv_bfloat16 g_w1lo[16384];

__device__ __forceinline__ long long ld_idx(const void* p, long long i, int is64) {
    return is64 ? ((const long long*)p)[i] : (long long)((const int*)p)[i];
}
__device__ __forceinline__ float silu_f(float x) { return x / (1.0f + __expf(-x)); }

__device__ __forceinline__ uint32_t smem_u32(const void* p) {
    uint32_t a;
    asm("{ .reg .u64 t; cvta.to.shared.u64 t, %1; cvt.u32.u64 %0, t; }" : "=r"(a) : "l"(p));
    return a;
}
__device__ __forceinline__ void ldsm_x4(uint32_t* r, uint32_t addr) {
    asm volatile("ldmatrix.sync.aligned.m8n8.x4.shared.b16 {%0,%1,%2,%3}, [%4];"
                 : "=r"(r[0]), "=r"(r[1]), "=r"(r[2]), "=r"(r[3]) : "r"(addr));
}
__device__ __forceinline__ void mma_bf16(float* d, const uint32_t* a,
                                         uint32_t b0, uint32_t b1) {
    asm volatile("mma.sync.aligned.m16n8k16.row.col.f32.bf16.bf16.f32 "
                 "{%0,%1,%2,%3}, {%4,%5,%6,%7}, {%8,%9}, {%0,%1,%2,%3};"
                 : "+f"(d[0]), "+f"(d[1]), "+f"(d[2]), "+f"(d[3])
                 : "r"(a[0]), "r"(a[1]), "r"(a[2]), "r"(a[3]), "r"(b0), "r"(b1));
}
__device__ __forceinline__ uint32_t pack_bf16x2(float x, float y) {
    __nv_bfloat16 bx = __float2bfloat16(x), by = __float2bfloat16(y);
    return (uint32_t)__bfloat16_as_ushort(bx) | ((uint32_t)__bfloat16_as_ushort(by) << 16);
}

// ---------------- misc kernels ----------------
__global__ void k_detect(const unsigned* __restrict__ ei) {
    int all0 = 1;
    for (int i = 0; i < 64; i++) all0 &= (ei[2 * i + 1] == 0u);
    g_is64 = all0;
}

__global__ void k_zero(int Nn) {
    long long i = (long long)blockIdx.x * blockDim.x + threadIdx.x;
    long long step = (long long)gridDim.x * blockDim.x;
    long long tot = (long long)Nn * DD;
    for (long long k = i; k < tot; k += step) g_agg[k] = 0.f;
    for (long long k = i; k < GG * DD; k += step) { g_sums[k] = 0.f; g_sq[k] = 0.f; }
    if (i < GG) g_cnt[(int)i] = 0;
}

// split both weight matrices into bf16 hi/lo, row-major [n][k]
__global__ void k_prep_w(const float* __restrict__ We, const float* __restrict__ W1) {
    int tid = threadIdx.x;
    for (int i = tid; i < 8192; i += 256) {
        int n = i >> 6, k2 = (i & 63) * 2;
        {
            float2 w = *(const float2*)(We + n * DD + k2);
            __nv_bfloat16 h0 = __float2bfloat16(w.x), h1 = __float2bfloat16(w.y);
            ((uint32_t*)g_whi)[i] = (uint32_t)__bfloat16_as_ushort(h0) |
                                    ((uint32_t)__bfloat16_as_ushort(h1) << 16);
            ((uint32_t*)g_wlo)[i] = pack_bf16x2(w.x - __bfloat162float(h0),
                                                w.y - __bfloat162float(h1));
        }
        {
            float2 w = *(const float2*)(W1 + n * DD + k2);
            __nv_bfloat16 h0 = __float2bfloat16(w.x), h1 = __float2bfloat16(w.y);
            ((uint32_t*)g_w1hi)[i] = (uint32_t)__bfloat16_as_ushort(h0) |
                                     ((uint32_t)__bfloat16_as_ushort(h1) << 16);
            ((uint32_t*)g_w1lo)[i] = pack_bf16x2(w.x - __bfloat162float(h0),
                                                 w.y - __bfloat162float(h1));
        }
    }
}

// ---------------- shared mma-tile machinery ----------------
// smem tiles: bf16 [128][128], row stride 272B (16B pad -> conflict-free ldmatrix)
#define TSTR 272
#define SM_AHI 0
#define SM_ALO 34816
#define SM_WHI 69632
#define SM_WLO 104448
#define SM_TILE_TOTAL 139264
#define DSTR 132   // staged D row stride in floats

// Fills W tiles + A(hi/lo) tiles, runs 3-pass split GEMM, stages D[128][128]
// into smem at offset 0 (DSTR stride). Must be followed by __syncthreads() done inside.
__device__ __forceinline__ void tile_gemm_stage(char* smem, uint32_t sb,
                                                const float* __restrict__ X,
                                                const __nv_bfloat16* __restrict__ Whi,
                                                const __nv_bfloat16* __restrict__ Wlo,
                                                long long r0, long long rows, int tid) {
    int wid = tid >> 5, lane = tid & 31;
    {
        const uint4* wh = (const uint4*)Whi;
        const uint4* wl = (const uint4*)Wlo;
        for (int i = tid; i < 2048; i += 256) {
            int row = i >> 4, q = i & 15;
            *(uint4*)(smem + SM_WHI + row * TSTR + q * 16) = wh[i];
            *(uint4*)(smem + SM_WLO + row * TSTR + q * 16) = wl[i];
        }
    }
    for (int i = tid; i < 4096; i += 256) {
        int row = i >> 5, q = i & 31;
        float4 a = make_float4(0.f, 0.f, 0.f, 0.f);
        if (r0 + row < rows) a = *(const float4*)(X + (r0 + row) * DD + q * 4);
        __nv_bfloat16 h0 = __float2bfloat16(a.x), h1 = __float2bfloat16(a.y);
        __nv_bfloat16 h2 = __float2bfloat16(a.z), h3 = __float2bfloat16(a.w);
        uint2 hv, lv;
        hv.x = (uint32_t)__bfloat16_as_ushort(h0) | ((uint32_t)__bfloat16_as_ushort(h1) << 16);
        hv.y = (uint32_t)__bfloat16_as_ushort(h2) | ((uint32_t)__bfloat16_as_ushort(h3) << 16);
        lv.x = pack_bf16x2(a.x - __bfloat162float(h0), a.y - __bfloat162float(h1));
        lv.y = pack_bf16x2(a.z - __bfloat162float(h2), a.w - __bfloat162float(h3));
        *(uint2*)(smem + SM_AHI + row * TSTR + q * 8) = hv;
        *(uint2*)(smem + SM_ALO + row * TSTR + q * 8) = lv;
    }
    __syncthreads();

    float acc[16][4];
#pragma unroll
    for (int i = 0; i < 16; i++)
#pragma unroll
        for (int j = 0; j < 4; j++) acc[i][j] = 0.f;

    int l16 = lane & 15;
    int lhalf = (lane >> 4) * 16;
    uint32_t arow = (uint32_t)(wid * 16 + l16) * TSTR + lhalf;

#pragma unroll 1
    for (int pass = 0; pass < 3; pass++) {
        uint32_t Ab = sb + (pass == 2 ? SM_ALO : SM_AHI);
        uint32_t Wb = sb + (pass == 1 ? SM_WLO : SM_WHI);
#pragma unroll 1
        for (int ks = 0; ks < 8; ks++) {
            uint32_t a[4];
            ldsm_x4(a, Ab + arow + ks * 32);
#pragma unroll
            for (int nbp = 0; nbp < 8; nbp++) {
                uint32_t b[4];
                ldsm_x4(b, Wb + (uint32_t)(nbp * 16 + l16) * TSTR + lhalf + ks * 32);
                mma_bf16(acc[2 * nbp], a, b[0], b[2]);
                mma_bf16(acc[2 * nbp + 1], a, b[1], b[3]);
            }
        }
    }
    __syncthreads();

    float* Ds = (float*)smem;
    {
        int rb = wid * 16 + (lane >> 2);
        int cb = (lane & 3) * 2;
#pragma unroll
        for (int nb = 0; nb < 16; nb++) {
            *(float2*)&Ds[rb * DSTR + nb * 8 + cb] = make_float2(acc[nb][0], acc[nb][1]);
            *(float2*)&Ds[(rb + 8) * DSTR + nb * 8 + cb] = make_float2(acc[nb][2], acc[nb][3]);
        }
    }
    __syncthreads();
}

// ---------------- node lin1 via mma ----------------
__global__ __launch_bounds__(256, 1) void k_node_mma(const float* __restrict__ X,
                                                     const float* __restrict__ bias,
                                                     int Nn) {
    extern __shared__ char smem[];
    uint32_t sb = smem_u32(smem);
    int tid = threadIdx.x;
    long long r0 = (long long)blockIdx.x * 128;
    tile_gemm_stage(smem, sb, X, g_w1hi, g_w1lo, r0, Nn, tid);

    float* Ds = (float*)smem;
    int row = tid >> 1, ch = (tid & 1) * 64;
    long long r = r0 + row;
    if (r < Nn) {
        const float* bp = bias + ch;
        float* op = g_h + r * DD + ch;
#pragma unroll
        for (int j = 0; j < 16; j++) {
            float4 dv = *(const float4*)&Ds[row * DSTR + ch + j * 4];
            float4 bb = *(const float4*)(bp + j * 4);
            *(float4*)(op + j * 4) = make_float4(dv.x + bb.x, dv.y + bb.y,
                                                 dv.z + bb.z, dv.w + bb.w);
        }
    }
}

// ---------------- edge kernel via mma + vector atomics ----------------
__global__ __launch_bounds__(256, 1) void k_edge_mma(const float* __restrict__ EA,
                                                     const float* __restrict__ bias,
                                                     const void* __restrict__ ei,
                                                     int Ee) {
    extern __shared__ char smem[];
    uint32_t sb = smem_u32(smem);
    int tid = threadIdx.x;
    long long r0 = (long long)blockIdx.x * 128;

    // hoist edge indices (L2-resident) before tile work
    int row = tid >> 1, ch = (tid & 1) * 64;
    long long e = r0 + row;
    long long s = 0, d = 0;
    int valid = (e < Ee);
    if (valid) {
        int is64 = g_is64;
        s = ld_idx(ei, e, is64);
        d = ld_idx(ei, (long long)Ee + e, is64);
    }

    tile_gemm_stage(smem, sb, EA, g_whi, g_wlo, r0, Ee, tid);

    float* Ds = (float*)smem;
    if (valid) {
        const float* hp = g_h + s * DD + ch;
        const float* bp = bias + ch;
        float4* ap = (float4*)(g_agg + d * DD + ch);
#pragma unroll
        for (int j = 0; j < 16; j++) {
            float4 dv = *(const float4*)&Ds[row * DSTR + ch + j * 4];
            float4 hv = *(const float4*)(hp + j * 4);
            float4 bb = *(const float4*)(bp + j * 4);
            float4 m;
            m.x = silu_f(dv.x + bb.x + hv.x);
            m.y = silu_f(dv.y + bb.y + hv.y);
            m.z = silu_f(dv.z + bb.z + hv.z);
            m.w = silu_f(dv.w + bb.w + hv.w);
            atomicAdd(ap + j, m);   // 128-bit RED (cc >= 9.0)
        }
    }
}

// ---------------- post kernels (GraphNorm) ----------------
__global__ void k_post1(const float* __restrict__ X, const void* __restrict__ batch,
                        const float* __restrict__ epsp, int Nn) {
    int c = threadIdx.x & 127;
    int half = threadIdx.x >> 7;
    long long n0 = (long long)blockIdx.x * 64 + half * 32;
    float ep = 1.0f + epsp[0];
    int is64 = g_is64;
    int curg = -1; float accv = 0.f; int cr = 0;
    for (int q = 0; q < 32; q++) {
        long long n = n0 + q;
        if (n >= Nn) break;
        long long off = n * DD + c;
        float conv = ep * g_h[off] + g_agg[off];
        float t = silu_f(conv) + X[off];
        g_t[off] = t;
        int g = (int)ld_idx(batch, n, is64);
        if (g != curg) {
            if (curg >= 0) {
                atomicAdd(&g_sums[curg * DD + c], accv);
                if (c == 0) atomicAdd(&g_cnt[curg], cr);
            }
            curg = g; accv = t; cr = 1;
        } else { accv += t; cr++; }
    }
    if (curg >= 0) {
        atomicAdd(&g_sums[curg * DD + c], accv);
        if (c == 0) atomicAdd(&g_cnt[curg], cr);
    }
}

__global__ void k_post2(const void* __restrict__ batch, const float* __restrict__ gms,
                        int Nn) {
    int c = threadIdx.x & 127;
    int half = threadIdx.x >> 7;
    long long n0 = (long long)blockIdx.x * 64 + half * 32;
    int is64 = g_is64;
    float msc = gms[c];
    int curg = -1; float mean = 0.f, ssq = 0.f;
    for (int q = 0; q < 32; q++) {
        long long n = n0 + q;
        if (n >= Nn) break;
        int g = (int)ld_idx(batch, n, is64);
        if (g != curg) {
            if (curg >= 0) atomicAdd(&g_sq[curg * DD + c], ssq);
            curg = g; ssq = 0.f;
            float cf = fmaxf((float)g_cnt[g], 1.f);
            mean = g_sums[g * DD + c] / cf;
        }
        long long off = n * DD + c;
        float o = g_t[off] - mean * msc;
        g_h[off] = o;
        ssq += o * o;
    }
    if (curg >= 0) atomicAdd(&g_sq[curg * DD + c], ssq);
}

__global__ void k_post3(const void* __restrict__ batch, const float* __restrict__ gw,
                        const float* __restrict__ gb, float* __restrict__ out, int Nn) {
    long long i = (long long)blockIdx.x * blockDim.x + threadIdx.x;
    long long step = (long long)gridDim.x * blockDim.x;
    long long tot = (long long)Nn * DD;
    int is64 = g_is64;
    for (long long k = i; k < tot; k += step) {
        long long n = k >> 7;
        int c = (int)(k & 127);
        int g = (int)ld_idx(batch, n, is64);
        float cf = fmaxf((float)g_cnt[g], 1.f);
        float stdv = sqrtf(g_sq[g * DD + c] / cf + 1e-5f);
        out[k] = gw[c] * g_h[k] / stdv + gb[c];
    }
}

// ---------------- launcher ----------------
extern "C" void kernel_launch(void* const* d_in, const int* in_sizes, int n_in,
                              void* d_out, int out_size) {
    const float* node_h    = (const float*)d_in[0];
    const float* edge_attr = (const float*)d_in[1];
    const void*  batch     = d_in[2];
    const void*  ei        = d_in[3];
    const float* w1  = (const float*)d_in[4];
    const float* b1  = (const float*)d_in[5];
    const float* we  = (const float*)d_in[6];
    const float* be  = (const float*)d_in[7];
    const float* eps = (const float*)d_in[8];
    const float* gnw = (const float*)d_in[9];
    const float* gnb = (const float*)d_in[10];
    const float* gms = (const float*)d_in[11];

    int Nn = in_sizes[0] / DD;
    int Ee = in_sizes[1] / DD;

    cudaFuncSetAttribute(k_node_mma, cudaFuncAttributeMaxDynamicSharedMemorySize,
                         SM_TILE_TOTAL);
    cudaFuncSetAttribute(k_edge_mma, cudaFuncAttributeMaxDynamicSharedMemorySize,
                         SM_TILE_TOTAL);

    k_detect<<<1, 1>>>((const unsigned*)ei);
    k_zero<<<1024, 256>>>(Nn);
    k_prep_w<<<1, 256>>>(we, w1);
    k_node_mma<<<(Nn + 127) / 128, 256, SM_TILE_TOTAL>>>(node_h, b1, Nn);
    k_edge_mma<<<(Ee + 127) / 128, 256, SM_TILE_TOTAL>>>(edge_attr, be, ei, Ee);
    k_post1<<<(Nn + 63) / 64, 256>>>(node_h, batch, eps, Nn);
    k_post2<<<(Nn + 63) / 64, 256>>>(batch, gms, Nn);
    k_post3<<<2048, 256>>>(batch, gnw, gnb, (float*)d_out, Nn);
}

// round 9
// speedup vs baseline: 1.8289x; 1.4279x over previous
#include <cuda_runtime.h>
#include <cuda_bf16.h>
#include <cstdint>

#define DD 128
#define MAXN 50000
#define GG 64

// ---------------- device scratch ----------------
__device__ float g_h[(size_t)MAXN * DD];
__device__ float g_agg[(size_t)MAXN * DD];
__device__ float g_t[(size_t)MAXN * DD];
__device__ float g_sums[GG * DD];
__device__ float g_sq[GG * DD];
__device__ int   g_cnt[GG];
__device__ int   g_is64;
// W in mma B-fragment order: [(ks*8+nbp)*32+lane] -> uint4(b0,b1,b2,b3)
__device__ __align__(16) uint4 g_wfe_hi[2048];   // edge lin hi
__device__ __align__(16) uint4 g_wfe_lo[2048];   // edge lin lo
__device__ __align__(16) uint4 g_wf1_hi[2048];   // node lin1 hi
__device__ __align__(16) uint4 g_wf1_lo[2048];   // node lin1 lo

__device__ __forceinline__ long long ld_idx(const void* p, long long i, int is64) {
    return is64 ? ((const long long*)p)[i] : (long long)((const int*)p)[i];
}
__device__ __forceinline__ float silu_f(float x) { return x / (1.0f + __expf(-x)); }

__device__ __forceinline__ uint32_t smem_u32(const void* p) {
    uint32_t a;
    asm("{ .reg .u64 t; cvta.to.shared.u64 t, %1; cvt.u32.u64 %0, t; }" : "=r"(a) : "l"(p));
    return a;
}
__device__ __forceinline__ void ldsm_x4(uint32_t* r, uint32_t addr) {
    asm volatile("ldmatrix.sync.aligned.m8n8.x4.shared.b16 {%0,%1,%2,%3}, [%4];"
                 : "=r"(r[0]), "=r"(r[1]), "=r"(r[2]), "=r"(r[3]) : "r"(addr));
}
__device__ __forceinline__ void mma_bf16(float* d, const uint32_t* a,
                                         uint32_t b0, uint32_t b1) {
    asm volatile("mma.sync.aligned.m16n8k16.row.col.f32.bf16.bf16.f32 "
                 "{%0,%1,%2,%3}, {%4,%5,%6,%7}, {%8,%9}, {%0,%1,%2,%3};"
                 : "+f"(d[0]), "+f"(d[1]), "+f"(d[2]), "+f"(d[3])
                 : "r"(a[0]), "r"(a[1]), "r"(a[2]), "r"(a[3]), "r"(b0), "r"(b1));
}
__device__ __forceinline__ uint32_t pack_bf16x2(float x, float y) {
    __nv_bfloat16 bx = __float2bfloat16(x), by = __float2bfloat16(y);
    return (uint32_t)__bfloat16_as_ushort(bx) | ((uint32_t)__bfloat16_as_ushort(by) << 16);
}
__device__ __forceinline__ uint32_t pack_hi2(float x, float y) {
    return pack_bf16x2(x, y);
}
__device__ __forceinline__ uint32_t pack_lo2(float x, float y) {
    float hx = __bfloat162float(__float2bfloat16(x));
    float hy = __bfloat162float(__float2bfloat16(y));
    return pack_bf16x2(x - hx, y - hy);
}

// ---------------- misc kernels ----------------
__global__ void k_detect(const unsigned* __restrict__ ei) {
    int all0 = 1;
    for (int i = 0; i < 64; i++) all0 &= (ei[2 * i + 1] == 0u);
    g_is64 = all0;
}

__global__ void k_zero(int Nn) {
    long long i = (long long)blockIdx.x * blockDim.x + threadIdx.x;
    long long step = (long long)gridDim.x * blockDim.x;
    long long tot = (long long)Nn * DD;
    for (long long k = i; k < tot; k += step) g_agg[k] = 0.f;
    for (long long k = i; k < GG * DD; k += step) { g_sums[k] = 0.f; g_sq[k] = 0.f; }
    if (i < GG) g_cnt[(int)i] = 0;
}

// Build W fragments directly from the known mma.sync B-fragment mapping:
// frag fi = ks*8+nbp, lane L:
//   b0 = W[n0  ][k0], W[n0  ][k0+1]   (n0 = nbp*16 + (L>>2), k0 = ks*16 + 2*(L&3))
//   b1 = W[n0+8][k0], W[n0+8][k0+1]
//   b2 = W[n0  ][k0+8], ...
//   b3 = W[n0+8][k0+8], ...
__global__ void k_prep_w(const float* __restrict__ We, const float* __restrict__ W1) {
    int tid = blockIdx.x * blockDim.x + threadIdx.x;   // 0..2047
    if (tid >= 2048) return;
    int fi = tid >> 5, lane = tid & 31;
    int ks = fi >> 3, nbp = fi & 7;
    int n0 = nbp * 16 + (lane >> 2);
    int k0 = ks * 16 + 2 * (lane & 3);
    {
        float2 w00 = *(const float2*)(We + n0 * DD + k0);
        float2 w10 = *(const float2*)(We + (n0 + 8) * DD + k0);
        float2 w01 = *(const float2*)(We + n0 * DD + k0 + 8);
        float2 w11 = *(const float2*)(We + (n0 + 8) * DD + k0 + 8);
        g_wfe_hi[tid] = make_uint4(pack_hi2(w00.x, w00.y), pack_hi2(w10.x, w10.y),
                                   pack_hi2(w01.x, w01.y), pack_hi2(w11.x, w11.y));
        g_wfe_lo[tid] = make_uint4(pack_lo2(w00.x, w00.y), pack_lo2(w10.x, w10.y),
                                   pack_lo2(w01.x, w01.y), pack_lo2(w11.x, w11.y));
    }
    {
        float2 w00 = *(const float2*)(W1 + n0 * DD + k0);
        float2 w10 = *(const float2*)(W1 + (n0 + 8) * DD + k0);
        float2 w01 = *(const float2*)(W1 + n0 * DD + k0 + 8);
        float2 w11 = *(const float2*)(W1 + (n0 + 8) * DD + k0 + 8);
        g_wf1_hi[tid] = make_uint4(pack_hi2(w00.x, w00.y), pack_hi2(w10.x, w10.y),
                                   pack_hi2(w01.x, w01.y), pack_hi2(w11.x, w11.y));
        g_wf1_lo[tid] = make_uint4(pack_lo2(w00.x, w00.y), pack_lo2(w10.x, w10.y),
                                   pack_lo2(w01.x, w01.y), pack_lo2(w11.x, w11.y));
    }
}

// ---------------- shared mma-tile machinery ----------------
// smem: A tiles only. bf16 [128][128], row stride 272B (16B pad, conflict-free ldmatrix)
#define TSTR 272
#define SM_AHI 0
#define SM_ALO 34816
#define SM_TILE_TOTAL 69632
#define DSTR 132   // staged D row stride in floats (D reuses tile region)

__device__ __forceinline__ void tile_gemm_stage(char* smem, uint32_t sb,
                                                const float* __restrict__ X,
                                                const uint4* __restrict__ Wfhi,
                                                const uint4* __restrict__ Wflo,
                                                long long r0, long long rows, int tid) {
    int wid = tid >> 5, lane = tid & 31;
    // fill A hi/lo tiles
    for (int i = tid; i < 4096; i += 256) {
        int row = i >> 5, q = i & 31;
        float4 a = make_float4(0.f, 0.f, 0.f, 0.f);
        if (r0 + row < rows) a = *(const float4*)(X + (r0 + row) * DD + q * 4);
        __nv_bfloat16 h0 = __float2bfloat16(a.x), h1 = __float2bfloat16(a.y);
        __nv_bfloat16 h2 = __float2bfloat16(a.z), h3 = __float2bfloat16(a.w);
        uint2 hv, lv;
        hv.x = (uint32_t)__bfloat16_as_ushort(h0) | ((uint32_t)__bfloat16_as_ushort(h1) << 16);
        hv.y = (uint32_t)__bfloat16_as_ushort(h2) | ((uint32_t)__bfloat16_as_ushort(h3) << 16);
        lv.x = pack_bf16x2(a.x - __bfloat162float(h0), a.y - __bfloat162float(h1));
        lv.y = pack_bf16x2(a.z - __bfloat162float(h2), a.w - __bfloat162float(h3));
        *(uint2*)(smem + SM_AHI + row * TSTR + q * 8) = hv;
        *(uint2*)(smem + SM_ALO + row * TSTR + q * 8) = lv;
    }
    __syncthreads();

    float acc[16][4];
#pragma unroll
    for (int i = 0; i < 16; i++)
#pragma unroll
        for (int j = 0; j < 4; j++) acc[i][j] = 0.f;

    int l16 = lane & 15;
    int lhalf = (lane >> 4) * 16;
    uint32_t arow = (uint32_t)(wid * 16 + l16) * TSTR + lhalf;

#pragma unroll 1
    for (int pass = 0; pass < 3; pass++) {
        uint32_t Ab = sb + (pass == 2 ? SM_ALO : SM_AHI);
        const uint4* Wf = (pass == 1 ? Wflo : Wfhi);
#pragma unroll 1
        for (int ks = 0; ks < 8; ks++) {
            uint32_t a[4];
            ldsm_x4(a, Ab + arow + ks * 32);
            const uint4* wp = Wf + (ks * 8) * 32 + lane;
#pragma unroll
            for (int nbp = 0; nbp < 8; nbp++) {
                uint4 b = wp[nbp * 32];
                mma_bf16(acc[2 * nbp], a, b.x, b.z);
                mma_bf16(acc[2 * nbp + 1], a, b.y, b.w);
            }
        }
    }
    __syncthreads();

    float* Ds = (float*)smem;
    {
        int rb = wid * 16 + (lane >> 2);
        int cb = (lane & 3) * 2;
#pragma unroll
        for (int nb = 0; nb < 16; nb++) {
            *(float2*)&Ds[rb * DSTR + nb * 8 + cb] = make_float2(acc[nb][0], acc[nb][1]);
            *(float2*)&Ds[(rb + 8) * DSTR + nb * 8 + cb] = make_float2(acc[nb][2], acc[nb][3]);
        }
    }
    __syncthreads();
}

// ---------------- node lin1 via mma ----------------
__global__ __launch_bounds__(256, 2) void k_node_mma(const float* __restrict__ X,
                                                     const float* __restrict__ bias,
                                                     int Nn) {
    extern __shared__ char smem[];
    uint32_t sb = smem_u32(smem);
    int tid = threadIdx.x;
    long long r0 = (long long)blockIdx.x * 128;
    tile_gemm_stage(smem, sb, X, g_wf1_hi, g_wf1_lo, r0, Nn, tid);

    float* Ds = (float*)smem;
    int row = tid >> 1, ch = (tid & 1) * 64;
    long long r = r0 + row;
    if (r < Nn) {
        const float* bp = bias + ch;
        float* op = g_h + r * DD + ch;
#pragma unroll
        for (int j = 0; j < 16; j++) {
            float4 dv = *(const float4*)&Ds[row * DSTR + ch + j * 4];
            float4 bb = *(const float4*)(bp + j * 4);
            *(float4*)(op + j * 4) = make_float4(dv.x + bb.x, dv.y + bb.y,
                                                 dv.z + bb.z, dv.w + bb.w);
        }
    }
}

// ---------------- edge kernel via mma + vector atomics ----------------
__global__ __launch_bounds__(256, 2) void k_edge_mma(const float* __restrict__ EA,
                                                     const float* __restrict__ bias,
                                                     const void* __restrict__ ei,
                                                     int Ee) {
    extern __shared__ char smem[];
    uint32_t sb = smem_u32(smem);
    int tid = threadIdx.x;
    long long r0 = (long long)blockIdx.x * 128;

    // hoist edge indices (L2-resident) before tile work
    int row = tid >> 1, ch = (tid & 1) * 64;
    long long e = r0 + row;
    long long s = 0, d = 0;
    int valid = (e < Ee);
    if (valid) {
        int is64 = g_is64;
        s = ld_idx(ei, e, is64);
        d = ld_idx(ei, (long long)Ee + e, is64);
    }

    tile_gemm_stage(smem, sb, EA, g_wfe_hi, g_wfe_lo, r0, Ee, tid);

    float* Ds = (float*)smem;
    if (valid) {
        const float* hp = g_h + s * DD + ch;
        const float* bp = bias + ch;
        float4* ap = (float4*)(g_agg + d * DD + ch);
#pragma unroll
        for (int j = 0; j < 16; j++) {
            float4 dv = *(const float4*)&Ds[row * DSTR + ch + j * 4];
            float4 hv = *(const float4*)(hp + j * 4);
            float4 bb = *(const float4*)(bp + j * 4);
            float4 m;
            m.x = silu_f(dv.x + bb.x + hv.x);
            m.y = silu_f(dv.y + bb.y + hv.y);
            m.z = silu_f(dv.z + bb.z + hv.z);
            m.w = silu_f(dv.w + bb.w + hv.w);
            atomicAdd(ap + j, m);   // 128-bit RED
        }
    }
}

// ---------------- post kernels (GraphNorm) ----------------
__global__ void k_post1(const float* __restrict__ X, const void* __restrict__ batch,
                        const float* __restrict__ epsp, int Nn) {
    int c = threadIdx.x & 127;
    int half = threadIdx.x >> 7;
    long long n0 = (long long)blockIdx.x * 64 + half * 32;
    float ep = 1.0f + epsp[0];
    int is64 = g_is64;
    int curg = -1; float accv = 0.f; int cr = 0;
    for (int q = 0; q < 32; q++) {
        long long n = n0 + q;
        if (n >= Nn) break;
        long long off = n * DD + c;
        float conv = ep * g_h[off] + g_agg[off];
        float t = silu_f(conv) + X[off];
        g_t[off] = t;
        int g = (int)ld_idx(batch, n, is64);
        if (g != curg) {
            if (curg >= 0) {
                atomicAdd(&g_sums[curg * DD + c], accv);
                if (c == 0) atomicAdd(&g_cnt[curg], cr);
            }
            curg = g; accv = t; cr = 1;
        } else { accv += t; cr++; }
    }
    if (curg >= 0) {
        atomicAdd(&g_sums[curg * DD + c], accv);
        if (c == 0) atomicAdd(&g_cnt[curg], cr);
    }
}

__global__ void k_post2(const void* __restrict__ batch, const float* __restrict__ gms,
                        int Nn) {
    int c = threadIdx.x & 127;
    int half = threadIdx.x >> 7;
    long long n0 = (long long)blockIdx.x * 64 + half * 32;
    int is64 = g_is64;
    float msc = gms[c];
    int curg = -1; float mean = 0.f, ssq = 0.f;
    for (int q = 0; q < 32; q++) {
        long long n = n0 + q;
        if (n >= Nn) break;
        int g = (int)ld_idx(batch, n, is64);
        if (g != curg) {
            if (curg >= 0) atomicAdd(&g_sq[curg * DD + c], ssq);
            curg = g; ssq = 0.f;
            float cf = fmaxf((float)g_cnt[g], 1.f);
            mean = g_sums[g * DD + c] / cf;
        }
        long long off = n * DD + c;
        float o = g_t[off] - mean * msc;
        g_h[off] = o;
        ssq += o * o;
    }
    if (curg >= 0) atomicAdd(&g_sq[curg * DD + c], ssq);
}

__global__ void k_post3(const void* __restrict__ batch, const float* __restrict__ gw,
                        const float* __restrict__ gb, float* __restrict__ out, int Nn) {
    long long i = (long long)blockIdx.x * blockDim.x + threadIdx.x;
    long long step = (long long)gridDim.x * blockDim.x;
    long long tot = (long long)Nn * DD;
    int is64 = g_is64;
    for (long long k = i; k < tot; k += step) {
        long long n = k >> 7;
        int c = (int)(k & 127);
        int g = (int)ld_idx(batch, n, is64);
        float cf = fmaxf((float)g_cnt[g], 1.f);
        float stdv = sqrtf(g_sq[g * DD + c] / cf + 1e-5f);
        out[k] = gw[c] * g_h[k] / stdv + gb[c];
    }
}

// ---------------- launcher ----------------
extern "C" void kernel_launch(void* const* d_in, const int* in_sizes, int n_in,
                              void* d_out, int out_size) {
    const float* node_h    = (const float*)d_in[0];
    const float* edge_attr = (const float*)d_in[1];
    const void*  batch     = d_in[2];
    const void*  ei        = d_in[3];
    const float* w1  = (const float*)d_in[4];
    const float* b1  = (const float*)d_in[5];
    const float* we  = (const float*)d_in[6];
    const float* be  = (const float*)d_in[7];
    const float* eps = (const float*)d_in[8];
    const float* gnw = (const float*)d_in[9];
    const float* gnb = (const float*)d_in[10];
    const float* gms = (const float*)d_in[11];

    int Nn = in_sizes[0] / DD;
    int Ee = in_sizes[1] / DD;

    cudaFuncSetAttribute(k_node_mma, cudaFuncAttributeMaxDynamicSharedMemorySize,
                         SM_TILE_TOTAL);
    cudaFuncSetAttribute(k_edge_mma, cudaFuncAttributeMaxDynamicSharedMemorySize,
                         SM_TILE_TOTAL);

    k_detect<<<1, 1>>>((const unsigned*)ei);
    k_zero<<<1024, 256>>>(Nn);
    k_prep_w<<<8, 256>>>(we, w1);
    k_node_mma<<<(Nn + 127) / 128, 256, SM_TILE_TOTAL>>>(node_h, b1, Nn);
    k_edge_mma<<<(Ee + 127) / 128, 256, SM_TILE_TOTAL>>>(edge_attr, be, ei, Ee);
    k_post1<<<(Nn + 63) / 64, 256>>>(node_h, batch, eps, Nn);
    k_post2<<<(Nn + 63) / 64, 256>>>(batch, gms, Nn);
    k_post3<<<2048, 256>>>(batch, gnw, gnb, (float*)d_out, Nn);
}

// round 11
// speedup vs baseline: 2.4671x; 1.3489x over previous
#include <cuda_runtime.h>
#include <cuda_bf16.h>
#include <cstdint>

#define DD 128
#define MAXN 50000
#define GG 64

// ---------------- device scratch ----------------
__device__ float g_h[(size_t)MAXN * DD];
__device__ float g_agg[(size_t)MAXN * DD];
__device__ float g_t[(size_t)MAXN * DD];
__device__ float g_sums[GG * DD];
__device__ float g_sq[GG * DD];
__device__ int   g_cnt[GG];
__device__ int   g_is64;
// W in mma B-fragment order: [(ks*8+nbp)*32+lane] -> uint4(b0,b1,b2,b3)
__device__ __align__(16) uint4 g_wfe_hi[2048];   // edge lin hi
__device__ __align__(16) uint4 g_wfe_lo[2048];   // edge lin lo
__device__ __align__(16) uint4 g_wf1_hi[2048];   // node lin1 hi
__device__ __align__(16) uint4 g_wf1_lo[2048];   // node lin1 lo

__device__ __forceinline__ long long ld_idx(const void* p, long long i, int is64) {
    return is64 ? ((const long long*)p)[i] : (long long)((const int*)p)[i];
}
__device__ __forceinline__ float silu_f(float x) { return x / (1.0f + __expf(-x)); }

__device__ __forceinline__ uint32_t smem_u32(const void* p) {
    uint32_t a;
    asm("{ .reg .u64 t; cvta.to.shared.u64 t, %1; cvt.u32.u64 %0, t; }" : "=r"(a) : "l"(p));
    return a;
}
__device__ __forceinline__ void cp_async16(uint32_t saddr, const void* g) {
    asm volatile("cp.async.cg.shared.global [%0], [%1], 16;"
                 :: "r"(saddr), "l"(g) : "memory");
}
__device__ __forceinline__ void cp_commit_wait() {
    asm volatile("cp.async.commit_group;" ::: "memory");
    asm volatile("cp.async.wait_group 0;" ::: "memory");
}
__device__ __forceinline__ void mma_bf16(float* d, const uint32_t* a,
                                         uint32_t b0, uint32_t b1) {
    asm volatile("mma.sync.aligned.m16n8k16.row.col.f32.bf16.bf16.f32 "
                 "{%0,%1,%2,%3}, {%4,%5,%6,%7}, {%8,%9}, {%0,%1,%2,%3};"
                 : "+f"(d[0]), "+f"(d[1]), "+f"(d[2]), "+f"(d[3])
                 : "r"(a[0]), "r"(a[1]), "r"(a[2]), "r"(a[3]), "r"(b0), "r"(b1));
}
__device__ __forceinline__ uint32_t pack_bf16x2(float x, float y) {
    __nv_bfloat16 bx = __float2bfloat16(x), by = __float2bfloat16(y);
    return (uint32_t)__bfloat16_as_ushort(bx) | ((uint32_t)__bfloat16_as_ushort(by) << 16);
}
__device__ __forceinline__ uint32_t pack_hi2(float x, float y) {
    return pack_bf16x2(x, y);
}
__device__ __forceinline__ uint32_t pack_lo2(float x, float y) {
    float hx = __bfloat162float(__float2bfloat16(x));
    float hy = __bfloat162float(__float2bfloat16(y));
    return pack_bf16x2(x - hx, y - hy);
}

// ---------------- misc kernels ----------------
__global__ void k_detect(const unsigned* __restrict__ ei) {
    int all0 = 1;
    for (int i = 0; i < 64; i++) all0 &= (ei[2 * i + 1] == 0u);
    g_is64 = all0;
}

__global__ void k_zero(int Nn) {
    long long i = (long long)blockIdx.x * blockDim.x + threadIdx.x;
    long long step = (long long)gridDim.x * blockDim.x;
    long long tot = (long long)Nn * DD;
    for (long long k = i; k < tot; k += step) g_agg[k] = 0.f;
    for (long long k = i; k < GG * DD; k += step) { g_sums[k] = 0.f; g_sq[k] = 0.f; }
    if (i < GG) g_cnt[(int)i] = 0;
}

// Build W fragments from the mma.sync B-fragment mapping:
// frag fi = ks*8+nbp, lane L:
//   b0 = W[n0  ][k0..k0+1]   (n0 = nbp*16 + (L>>2), k0 = ks*16 + 2*(L&3))
//   b1 = W[n0+8][k0..k0+1], b2 = W[n0][k0+8..], b3 = W[n0+8][k0+8..]
__global__ void k_prep_w(const float* __restrict__ We, const float* __restrict__ W1) {
    int tid = blockIdx.x * blockDim.x + threadIdx.x;   // 0..2047
    if (tid >= 2048) return;
    int fi = tid >> 5, lane = tid & 31;
    int ks = fi >> 3, nbp = fi & 7;
    int n0 = nbp * 16 + (lane >> 2);
    int k0 = ks * 16 + 2 * (lane & 3);
    {
        float2 w00 = *(const float2*)(We + n0 * DD + k0);
        float2 w10 = *(const float2*)(We + (n0 + 8) * DD + k0);
        float2 w01 = *(const float2*)(We + n0 * DD + k0 + 8);
        float2 w11 = *(const float2*)(We + (n0 + 8) * DD + k0 + 8);
        g_wfe_hi[tid] = make_uint4(pack_hi2(w00.x, w00.y), pack_hi2(w10.x, w10.y),
                                   pack_hi2(w01.x, w01.y), pack_hi2(w11.x, w11.y));
        g_wfe_lo[tid] = make_uint4(pack_lo2(w00.x, w00.y), pack_lo2(w10.x, w10.y),
                                   pack_lo2(w01.x, w01.y), pack_lo2(w11.x, w11.y));
    }
    {
        float2 w00 = *(const float2*)(W1 + n0 * DD + k0);
        float2 w10 = *(const float2*)(W1 + (n0 + 8) * DD + k0);
        float2 w01 = *(const float2*)(W1 + n0 * DD + k0 + 8);
        float2 w11 = *(const float2*)(W1 + (n0 + 8) * DD + k0 + 8);
        g_wf1_hi[tid] = make_uint4(pack_hi2(w00.x, w00.y), pack_hi2(w10.x, w10.y),
                                   pack_hi2(w01.x, w01.y), pack_hi2(w11.x, w11.y));
        g_wf1_lo[tid] = make_uint4(pack_lo2(w00.x, w00.y), pack_lo2(w10.x, w10.y),
                                   pack_lo2(w01.x, w01.y), pack_lo2(w11.x, w11.y));
    }
}

// ---------------- shared mma-tile machinery ----------------
// smem: one fp32 A tile [128][ASTRIDE]; reused for D staging (DSTR).
#define ASTRIDE 136          // floats per row: conflict-free LDS.64 fragment reads
#define SM_TILE_TOTAL (128 * ASTRIDE * 4)   // 69632 B -> 2 CTAs/SM
#define DSTR 132             // staged D row stride in floats

// OOB note: D rows depend only on the same A row, and OOB D rows are discarded
// by the epilogue valid-guard, so OOB source rows are simply clamped (garbage ok).
__device__ __forceinline__ void tile_gemm_stage(char* smem, uint32_t sb,
                                                const float* __restrict__ X,
                                                const uint4* __restrict__ Wfhi,
                                                const uint4* __restrict__ Wflo,
                                                long long r0, long long rows, int tid) {
    int wid = tid >> 5, lane = tid & 31;

    // async fill of raw fp32 A tile (clamped rows for OOB)
#pragma unroll
    for (int i = 0; i < 16; i++) {
        int idx = tid + i * 256;          // 0..4095
        int row = idx >> 5, q = idx & 31; // q: 16B chunk within 512B row
        uint32_t sa = sb + (uint32_t)(row * ASTRIDE + q * 4) * 4;
        long long gr = r0 + row;
        if (gr >= rows) gr = rows - 1;
        cp_async16(sa, X + gr * DD + q * 4);
    }
    cp_commit_wait();
    __syncthreads();

    const float* As = (const float*)smem;
    float acc[16][4];
#pragma unroll
    for (int i = 0; i < 16; i++)
#pragma unroll
        for (int j = 0; j < 4; j++) acc[i][j] = 0.f;

    int rowA = wid * 16 + (lane >> 2);
    int kcol = 2 * (lane & 3);
    const float* As0 = As + rowA * ASTRIDE;
    const float* As1 = As + (rowA + 8) * ASTRIDE;

#pragma unroll 1
    for (int ks = 0; ks < 8; ks++) {
        int kb = ks * 16 + kcol;
        float2 x0 = *(const float2*)(As0 + kb);
        float2 x1 = *(const float2*)(As1 + kb);
        float2 x2 = *(const float2*)(As0 + kb + 8);
        float2 x3 = *(const float2*)(As1 + kb + 8);
        uint32_t ahi[4] = { pack_hi2(x0.x, x0.y), pack_hi2(x1.x, x1.y),
                            pack_hi2(x2.x, x2.y), pack_hi2(x3.x, x3.y) };
        uint32_t alo[4] = { pack_lo2(x0.x, x0.y), pack_lo2(x1.x, x1.y),
                            pack_lo2(x2.x, x2.y), pack_lo2(x3.x, x3.y) };
        const uint4* wph = Wfhi + ks * 256 + lane;
        const uint4* wpl = Wflo + ks * 256 + lane;
#pragma unroll
        for (int nbp = 0; nbp < 8; nbp++) {
            uint4 bh = wph[nbp * 32];
            uint4 bl = wpl[nbp * 32];
            mma_bf16(acc[2 * nbp], ahi, bh.x, bh.z);
            mma_bf16(acc[2 * nbp + 1], ahi, bh.y, bh.w);
            mma_bf16(acc[2 * nbp], ahi, bl.x, bl.z);
            mma_bf16(acc[2 * nbp + 1], ahi, bl.y, bl.w);
            mma_bf16(acc[2 * nbp], alo, bh.x, bh.z);
            mma_bf16(acc[2 * nbp + 1], alo, bh.y, bh.w);
        }
    }
    __syncthreads();

    // stage D (reuse tile region)
    float* Ds = (float*)smem;
    {
        int rb = wid * 16 + (lane >> 2);
        int cb = (lane & 3) * 2;
#pragma unroll
        for (int nb = 0; nb < 16; nb++) {
            *(float2*)&Ds[rb * DSTR + nb * 8 + cb] = make_float2(acc[nb][0], acc[nb][1]);
            *(float2*)&Ds[(rb + 8) * DSTR + nb * 8 + cb] = make_float2(acc[nb][2], acc[nb][3]);
        }
    }
    __syncthreads();
}

// ---------------- node lin1 via mma ----------------
__global__ __launch_bounds__(256, 2) void k_node_mma(const float* __restrict__ X,
                                                     const float* __restrict__ bias,
                                                     int Nn) {
    extern __shared__ char smem[];
    uint32_t sb = smem_u32(smem);
    int tid = threadIdx.x;
    long long r0 = (long long)blockIdx.x * 128;
    tile_gemm_stage(smem, sb, X, g_wf1_hi, g_wf1_lo, r0, Nn, tid);

    float* Ds = (float*)smem;
    int row = tid >> 1, ch = (tid & 1) * 64;
    long long r = r0 + row;
    if (r < Nn) {
        const float* bp = bias + ch;
        float* op = g_h + r * DD + ch;
#pragma unroll
        for (int j = 0; j < 16; j++) {
            float4 dv = *(const float4*)&Ds[row * DSTR + ch + j * 4];
            float4 bb = *(const float4*)(bp + j * 4);
            *(float4*)(op + j * 4) = make_float4(dv.x + bb.x, dv.y + bb.y,
                                                 dv.z + bb.z, dv.w + bb.w);
        }
    }
}

// ---------------- edge kernel via mma + vector atomics ----------------
__global__ __launch_bounds__(256, 2) void k_edge_mma(const float* __restrict__ EA,
                                                     const float* __restrict__ bias,
                                                     const void* __restrict__ ei,
                                                     int Ee) {
    extern __shared__ char smem[];
    uint32_t sb = smem_u32(smem);
    int tid = threadIdx.x;
    long long r0 = (long long)blockIdx.x * 128;

    // hoist edge indices (L2-resident) before tile work
    int row = tid >> 1, ch = (tid & 1) * 64;
    long long e = r0 + row;
    long long s = 0, d = 0;
    int valid = (e < Ee);
    if (valid) {
        int is64 = g_is64;
        s = ld_idx(ei, e, is64);
        d = ld_idx(ei, (long long)Ee + e, is64);
    }

    tile_gemm_stage(smem, sb, EA, g_wfe_hi, g_wfe_lo, r0, Ee, tid);

    float* Ds = (float*)smem;
    if (valid) {
        const float* hp = g_h + s * DD + ch;
        const float* bp = bias + ch;
        float4* ap = (float4*)(g_agg + d * DD + ch);
#pragma unroll
        for (int j = 0; j < 16; j++) {
            float4 dv = *(const float4*)&Ds[row * DSTR + ch + j * 4];
            float4 hv = *(const float4*)(hp + j * 4);
            float4 bb = *(const float4*)(bp + j * 4);
            float4 m;
            m.x = silu_f(dv.x + bb.x + hv.x);
            m.y = silu_f(dv.y + bb.y + hv.y);
            m.z = silu_f(dv.z + bb.z + hv.z);
            m.w = silu_f(dv.w + bb.w + hv.w);
            atomicAdd(ap + j, m);   // 128-bit RED
        }
    }
}

// ---------------- post kernels (GraphNorm) ----------------
__global__ void k_post1(const float* __restrict__ X, const void* __restrict__ batch,
                        const float* __restrict__ epsp, int Nn) {
    int c = threadIdx.x & 127;
    int half = threadIdx.x >> 7;
    long long n0 = (long long)blockIdx.x * 64 + half * 32;
    float ep = 1.0f + epsp[0];
    int is64 = g_is64;
    int curg = -1; float accv = 0.f; int cr = 0;
    for (int q = 0; q < 32; q++) {
        long long n = n0 + q;
        if (n >= Nn) break;
        long long off = n * DD + c;
        float conv = ep * g_h[off] + g_agg[off];
        float t = silu_f(conv) + X[off];
        g_t[off] = t;
        int g = (int)ld_idx(batch, n, is64);
        if (g != curg) {
            if (curg >= 0) {
                atomicAdd(&g_sums[curg * DD + c], accv);
                if (c == 0) atomicAdd(&g_cnt[curg], cr);
            }
            curg = g; accv = t; cr = 1;
        } else { accv += t; cr++; }
    }
    if (curg >= 0) {
        atomicAdd(&g_sums[curg * DD + c], accv);
        if (c == 0) atomicAdd(&g_cnt[curg], cr);
    }
}

__global__ void k_post2(const void* __restrict__ batch, const float* __restrict__ gms,
                        int Nn) {
    int c = threadIdx.x & 127;
    int half = threadIdx.x >> 7;
    long long n0 = (long long)blockIdx.x * 64 + half * 32;
    int is64 = g_is64;
    float msc = gms[c];
    int curg = -1; float mean = 0.f, ssq = 0.f;
    for (int q = 0; q < 32; q++) {
        long long n = n0 + q;
        if (n >= Nn) break;
        int g = (int)ld_idx(batch, n, is64);
        if (g != curg) {
            if (curg >= 0) atomicAdd(&g_sq[curg * DD + c], ssq);
            curg = g; ssq = 0.f;
            float cf = fmaxf((float)g_cnt[g], 1.f);
            mean = g_sums[g * DD + c] / cf;
        }
        long long off = n * DD + c;
        float o = g_t[off] - mean * msc;
        g_h[off] = o;
        ssq += o * o;
    }
    if (curg >= 0) atomicAdd(&g_sq[curg * DD + c], ssq);
}

__global__ void k_post3(const void* __restrict__ batch, const float* __restrict__ gw,
                        const float* __restrict__ gb, float* __restrict__ out, int Nn) {
    long long i = (long long)blockIdx.x * blockDim.x + threadIdx.x;
    long long step = (long long)gridDim.x * blockDim.x;
    long long tot = (long long)Nn * DD;
    int is64 = g_is64;
    for (long long k = i; k < tot; k += step) {
        long long n = k >> 7;
        int c = (int)(k & 127);
        int g = (int)ld_idx(batch, n, is64);
        float cf = fmaxf((float)g_cnt[g], 1.f);
        float stdv = sqrtf(g_sq[g * DD + c] / cf + 1e-5f);
        out[k] = gw[c] * g_h[k] / stdv + gb[c];
    }
}

// ---------------- launcher ----------------
extern "C" void kernel_launch(void* const* d_in, const int* in_sizes, int n_in,
                              void* d_out, int out_size) {
    const float* node_h    = (const float*)d_in[0];
    const float* edge_attr = (const float*)d_in[1];
    const void*  batch     = d_in[2];
    const void*  ei        = d_in[3];
    const float* w1  = (const float*)d_in[4];
    const float* b1  = (const float*)d_in[5];
    const float* we  = (const float*)d_in[6];
    const float* be  = (const float*)d_in[7];
    const float* eps = (const float*)d_in[8];
    const float* gnw = (const float*)d_in[9];
    const float* gnb = (const float*)d_in[10];
    const float* gms = (const float*)d_in[11];

    int Nn = in_sizes[0] / DD;
    int Ee = in_sizes[1] / DD;

    cudaFuncSetAttribute(k_node_mma, cudaFuncAttributeMaxDynamicSharedMemorySize,
                         SM_TILE_TOTAL);
    cudaFuncSetAttribute(k_edge_mma, cudaFuncAttributeMaxDynamicSharedMemorySize,
                         SM_TILE_TOTAL);

    k_detect<<<1, 1>>>((const unsigned*)ei);
    k_zero<<<1024, 256>>>(Nn);
    k_prep_w<<<8, 256>>>(we, w1);
    k_node_mma<<<(Nn + 127) / 128, 256, SM_TILE_TOTAL>>>(node_h, b1, Nn);
    k_edge_mma<<<(Ee + 127) / 128, 256, SM_TILE_TOTAL>>>(edge_attr, be, ei, Ee);
    k_post1<<<(Nn + 63) / 64, 256>>>(node_h, batch, eps, Nn);
    k_post2<<<(Nn + 63) / 64, 256>>>(batch, gms, Nn);
    k_post3<<<2048, 256>>>(batch, gnw, gnb, (float*)d_out, Nn);
}